// round 1
// baseline (speedup 1.0000x reference)
#include <cuda_runtime.h>
#include <cuda_bf16.h>
#include <math.h>

// Problem constants (fixed shapes)
#define NN   50000
#define EE   800000
#define FIN  128
#define HEADS 8
#define HID  32
#define OUTC 4
#define HC1  (HEADS*HID)   // 256
#define HC2  (HEADS*OUTC)  // 32
#define NEG  0.2f

#define SCAN_B 1024
#define NBLK   ((NN + SCAN_B - 1) / SCAN_B)   // 49

// ---------------- scratch (__device__ globals; no runtime allocation) -------
__device__ float g_h1[NN * HC1];        // x @ W1
__device__ float g_o1[NN * HC1];        // layer-1 output (bias + lrelu applied)
__device__ float g_h2[NN * HC2];        // o1 @ W2
__device__ float g_asrc1[NN * HEADS], g_adst1[NN * HEADS];
__device__ float g_asrc2[NN * HEADS], g_adst2[NN * HEADS];
__device__ int   g_rowptr[NN + 1];
__device__ int   g_counts[NN];          // reused as scatter cursor
__device__ int   g_csrsrc[EE + NN];
__device__ int   g_blocksums[NBLK + 1];
__device__ int   g_blockoffs[NBLK + 1];

// ---------------- SGEMM: C[M,N] = A[M,K] @ B[K,N], row-major ----------------
template<int BM, int BN, int BK, int TM, int TN>
__global__ void sgemm_kernel(int M, int N, int K,
                             const float* __restrict__ A,
                             const float* __restrict__ B,
                             float* __restrict__ C) {
    constexpr int THREADS = (BM / TM) * (BN / TN);
    __shared__ float As[BK][BM];
    __shared__ float Bs[BK][BN];

    const int tid = threadIdx.x;
    const int blockRow = blockIdx.y * BM;
    const int blockCol = blockIdx.x * BN;
    const int tCol = (tid % (BN / TN)) * TN;
    const int tRow = (tid / (BN / TN)) * TM;

    float acc[TM][TN];
#pragma unroll
    for (int i = 0; i < TM; i++)
#pragma unroll
        for (int j = 0; j < TN; j++) acc[i][j] = 0.f;

    for (int k0 = 0; k0 < K; k0 += BK) {
        // load A tile (transposed into As[k][m])
        for (int i = tid; i < BM * BK; i += THREADS) {
            int m = i / BK, k = i % BK;
            int gm = blockRow + m;
            As[k][m] = (gm < M) ? A[(size_t)gm * K + k0 + k] : 0.f;
        }
        // load B tile
        for (int i = tid; i < BK * BN; i += THREADS) {
            int k = i / BN, n = i % BN;
            Bs[k][n] = B[(size_t)(k0 + k) * N + blockCol + n];
        }
        __syncthreads();

#pragma unroll
        for (int kk = 0; kk < BK; kk++) {
            float4 a4 = *(const float4*)&As[kk][tRow];
            float4 b4 = *(const float4*)&Bs[kk][tCol];
            float ra[4] = {a4.x, a4.y, a4.z, a4.w};
            float rb[4] = {b4.x, b4.y, b4.z, b4.w};
#pragma unroll
            for (int i = 0; i < TM; i++)
#pragma unroll
                for (int j = 0; j < TN; j++)
                    acc[i][j] = fmaf(ra[i], rb[j], acc[i][j]);
        }
        __syncthreads();
    }

#pragma unroll
    for (int i = 0; i < TM; i++) {
        int gm = blockRow + tRow + i;
        if (gm < M) {
            float4 v = make_float4(acc[i][0], acc[i][1], acc[i][2], acc[i][3]);
            *(float4*)&C[(size_t)gm * N + blockCol + tCol] = v;
        }
    }
}

// ---------------- alpha dot products: asrc[n,h], adst[n,h] ------------------
__global__ void alphas_kernel(const float* __restrict__ h,
                              const float* __restrict__ a_src,
                              const float* __restrict__ a_dst,
                              float* __restrict__ asrc,
                              float* __restrict__ adst, int C) {
    int i = blockIdx.x * blockDim.x + threadIdx.x;   // i = n*HEADS + head
    if (i >= NN * HEADS) return;
    int hh = i & (HEADS - 1);
    const float* hp = h + (size_t)(i >> 3) * (HEADS * C) + hh * C;
    float s1 = 0.f, s2 = 0.f;
    for (int c = 0; c < C; c++) {
        float v = hp[c];
        s1 = fmaf(v, a_src[hh * C + c], s1);
        s2 = fmaf(v, a_dst[hh * C + c], s2);
    }
    asrc[i] = s1;
    adst[i] = s2;
}

// ---------------- CSR construction ------------------------------------------
__global__ void init_counts_kernel() {
    int i = blockIdx.x * blockDim.x + threadIdx.x;
    if (i < NN) g_counts[i] = 1;   // reserve slot for self-loop
}

__global__ void count_kernel(const int* __restrict__ dst) {
    int e = blockIdx.x * blockDim.x + threadIdx.x;
    if (e < EE) atomicAdd(&g_counts[dst[e]], 1);
}

__global__ void scan_blocks_kernel() {
    __shared__ int sh[SCAN_B];
    int t = threadIdx.x;
    int i = blockIdx.x * SCAN_B + t;
    int v = (i < NN) ? g_counts[i] : 0;
    sh[t] = v;
    __syncthreads();
    for (int off = 1; off < SCAN_B; off <<= 1) {
        int x = (t >= off) ? sh[t - off] : 0;
        __syncthreads();
        sh[t] += x;
        __syncthreads();
    }
    if (i < NN) g_rowptr[i + 1] = sh[t];
    if (t == SCAN_B - 1) g_blocksums[blockIdx.x] = sh[t];
}

__global__ void scan_sums_kernel() {
    if (threadIdx.x == 0) {
        int run = 0;
        for (int b = 0; b < NBLK; b++) {
            g_blockoffs[b] = run;
            run += g_blocksums[b];
        }
        g_rowptr[0] = 0;
    }
}

__global__ void scan_add_kernel() {
    int i = blockIdx.x * blockDim.x + threadIdx.x;
    if (i < NN) g_rowptr[i + 1] += g_blockoffs[i / SCAN_B];
}

__global__ void place_self_kernel() {
    int i = blockIdx.x * blockDim.x + threadIdx.x;
    if (i < NN) {
        int p = g_rowptr[i];
        g_csrsrc[p] = i;        // self loop first
        g_counts[i] = p + 1;    // cursor for remaining edges
    }
}

__global__ void scatter_kernel(const int* __restrict__ src,
                               const int* __restrict__ dst) {
    int e = blockIdx.x * blockDim.x + threadIdx.x;
    if (e < EE) {
        int p = atomicAdd(&g_counts[dst[e]], 1);
        g_csrsrc[p] = src[e];
    }
}

// ---------------- aggregation: layer 1 (C=32), warp per dst node ------------
// out[n, h*32 + c] = lrelu( sum_e w_e * h[src_e, h*32+c] + b[h*32+c] )
__global__ void agg1_kernel(const float* __restrict__ h,
                            const float* __restrict__ asrc,
                            const float* __restrict__ adst,
                            const float* __restrict__ bias,
                            float* __restrict__ out) {
    int warp = (blockIdx.x * blockDim.x + threadIdx.x) >> 5;
    int lane = threadIdx.x & 31;
    if (warp >= NN) return;

    int beg = g_rowptr[warp];
    int end = g_rowptr[warp + 1];

    float adst_l = (lane < HEADS) ? adst[warp * HEADS + lane] : 0.f;

    // pass 1: per-head max (lanes 0..7 track their head)
    float amax_l = -INFINITY;
    for (int j = beg; j < end; j++) {
        int s = g_csrsrc[j];
        if (lane < HEADS) {
            float a = asrc[s * HEADS + lane] + adst_l;
            a = (a > 0.f) ? a : NEG * a;
            amax_l = fmaxf(amax_l, a);
        }
    }

    // pass 2: exp-sum + weighted message accumulation (division deferred)
    float denom_l = 0.f;
    float acc[HEADS];
#pragma unroll
    for (int k = 0; k < HEADS; k++) acc[k] = 0.f;

    for (int j = beg; j < end; j++) {
        int s = g_csrsrc[j];
        float ex = 0.f;
        if (lane < HEADS) {
            float a = asrc[s * HEADS + lane] + adst_l;
            a = (a > 0.f) ? a : NEG * a;
            ex = __expf(a - amax_l);
            denom_l += ex;
        }
        const float* hp = h + (size_t)s * HC1 + lane;
#pragma unroll
        for (int hh = 0; hh < HEADS; hh++) {
            float eh = __shfl_sync(0xffffffffu, ex, hh);
            acc[hh] = fmaf(hp[hh * HID], eh, acc[hh]);
        }
    }

#pragma unroll
    for (int hh = 0; hh < HEADS; hh++) {
        float dh = __shfl_sync(0xffffffffu, denom_l, hh);
        float v = acc[hh] / (dh + 1e-16f) + bias[hh * HID + lane];
        v = (v > 0.f) ? v : NEG * v;   // leaky relu between layers (fused)
        out[(size_t)warp * HC1 + hh * HID + lane] = v;
    }
}

// ---------------- aggregation: layer 2 (C=4), warp per dst node -------------
// lane = head*4 + c. No shuffles needed (denom replicated per 4-lane group).
__global__ void agg2_kernel(const float* __restrict__ h,
                            const float* __restrict__ asrc,
                            const float* __restrict__ adst,
                            const float* __restrict__ bias,
                            float* __restrict__ out) {
    int warp = (blockIdx.x * blockDim.x + threadIdx.x) >> 5;
    int lane = threadIdx.x & 31;
    if (warp >= NN) return;

    int beg = g_rowptr[warp];
    int end = g_rowptr[warp + 1];
    int hh = lane >> 2;

    float adst_l = adst[warp * HEADS + hh];

    float amax_l = -INFINITY;
    for (int j = beg; j < end; j++) {
        int s = g_csrsrc[j];
        float a = asrc[s * HEADS + hh] + adst_l;
        a = (a > 0.f) ? a : NEG * a;
        amax_l = fmaxf(amax_l, a);
    }

    float denom_l = 0.f;
    float acc = 0.f;
    for (int j = beg; j < end; j++) {
        int s = g_csrsrc[j];
        float a = asrc[s * HEADS + hh] + adst_l;
        a = (a > 0.f) ? a : NEG * a;
        float ex = __expf(a - amax_l);
        denom_l += ex;
        acc = fmaf(h[(size_t)s * HC2 + lane], ex, acc);
    }

    out[(size_t)warp * HC2 + lane] = acc / (denom_l + 1e-16f) + bias[lane];
}

// ---------------- launch ------------------------------------------------------
extern "C" void kernel_launch(void* const* d_in, const int* in_sizes, int n_in,
                              void* d_out, int out_size) {
    const float* x      = (const float*)d_in[0];
    const int*   ei     = (const int*)d_in[1];   // [2, E]: row 0 = src, row 1 = dst
    const float* W1     = (const float*)d_in[2];
    const float* a_src1 = (const float*)d_in[3];
    const float* a_dst1 = (const float*)d_in[4];
    const float* b1     = (const float*)d_in[5];
    const float* W2     = (const float*)d_in[6];
    const float* a_src2 = (const float*)d_in[7];
    const float* a_dst2 = (const float*)d_in[8];
    const float* b2     = (const float*)d_in[9];
    float* out = (float*)d_out;

    const int* src = ei;
    const int* dst = ei + EE;

    float *h1, *o1, *h2, *as1, *ad1, *as2, *ad2;
    cudaGetSymbolAddress((void**)&h1,  g_h1);
    cudaGetSymbolAddress((void**)&o1,  g_o1);
    cudaGetSymbolAddress((void**)&h2,  g_h2);
    cudaGetSymbolAddress((void**)&as1, g_asrc1);
    cudaGetSymbolAddress((void**)&ad1, g_adst1);
    cudaGetSymbolAddress((void**)&as2, g_asrc2);
    cudaGetSymbolAddress((void**)&ad2, g_adst2);

    // --- CSR build (independent of GEMMs; sequenced on same stream) ---
    init_counts_kernel<<<(NN + 255) / 256, 256>>>();
    count_kernel<<<(EE + 255) / 256, 256>>>(dst);
    scan_blocks_kernel<<<NBLK, SCAN_B>>>();
    scan_sums_kernel<<<1, 32>>>();
    scan_add_kernel<<<(NN + 255) / 256, 256>>>();
    place_self_kernel<<<(NN + 255) / 256, 256>>>();
    scatter_kernel<<<(EE + 255) / 256, 256>>>(src, dst);

    // --- layer 1 ---
    {
        dim3 grid(HC1 / 64, (NN + 63) / 64);
        sgemm_kernel<64, 64, 16, 4, 4><<<grid, 256>>>(NN, HC1, FIN, x, W1, h1);
    }
    alphas_kernel<<<(NN * HEADS + 255) / 256, 256>>>(h1, a_src1, a_dst1, as1, ad1, HID);
    agg1_kernel<<<(NN * 32 + 255) / 256, 256>>>(h1, as1, ad1, b1, o1);

    // --- layer 2 ---
    {
        dim3 grid(HC2 / 32, (NN + 63) / 64);
        sgemm_kernel<64, 32, 32, 4, 4><<<grid, 128>>>(NN, HC2, HC1, o1, W2, h2);
    }
    alphas_kernel<<<(NN * HEADS + 255) / 256, 256>>>(h2, a_src2, a_dst2, as2, ad2, OUTC);
    agg2_kernel<<<(NN * 32 + 255) / 256, 256>>>(h2, as2, ad2, b2, out);
}

// round 2
// speedup vs baseline: 1.3587x; 1.3587x over previous
#include <cuda_runtime.h>
#include <cuda_bf16.h>
#include <math.h>

// Problem constants (fixed shapes)
#define NN   50000
#define EE   800000
#define FIN  128
#define HEADS 8
#define HID  32
#define OUTC 4
#define HC1  (HEADS*HID)   // 256
#define HC2  (HEADS*OUTC)  // 32
#define NEG  0.2f

#define SCAN_B 1024
#define NBLK   ((NN + SCAN_B - 1) / SCAN_B)   // 49

// ---------------- scratch (__device__ globals; no runtime allocation) -------
__device__ float g_h1[NN * HC1];        // x @ W1
__device__ float g_o1[NN * HC1];        // layer-1 output (bias + lrelu applied)
__device__ float g_h2[NN * HC2];        // o1 @ W2
__device__ float g_asrc1[NN * HEADS], g_adst1[NN * HEADS];
__device__ float g_asrc2[NN * HEADS], g_adst2[NN * HEADS];
__device__ int   g_rowptr[NN + 1];
__device__ int   g_counts[NN];          // reused as scatter cursor
__device__ int   g_csrsrc[EE + NN];
__device__ int   g_blocksums[NBLK + 1];
__device__ int   g_blockoffs[NBLK + 1];

// ---------------- SGEMM: C[M,N] = A[M,K] @ B[K,N], row-major ----------------
// float4 loads, padded smem, register-blocked TMxTN.
template<int BM, int BN, int BK, int TM, int TN>
__global__ void sgemm_kernel(int M, int N, int K,
                             const float* __restrict__ A,
                             const float* __restrict__ B,
                             float* __restrict__ C) {
    constexpr int THREADS = (BM / TM) * (BN / TN);
    constexpr int KV = BK / 4;
    constexpr int NV = BN / 4;
    __shared__ float As[BK][BM + 4];
    __shared__ float Bs[BK][BN + 4];

    const int tid = threadIdx.x;
    const int blockRow = blockIdx.y * BM;
    const int blockCol = blockIdx.x * BN;
    const int tCol = (tid % (BN / TN)) * TN;
    const int tRow = (tid / (BN / TN)) * TM;

    float acc[TM][TN];
#pragma unroll
    for (int i = 0; i < TM; i++)
#pragma unroll
        for (int j = 0; j < TN; j++) acc[i][j] = 0.f;

    for (int k0 = 0; k0 < K; k0 += BK) {
        // load A tile (transposed into As[k][m]) with float4 gmem reads
#pragma unroll
        for (int i = tid; i < BM * KV; i += THREADS) {
            int m = i / KV, k4 = i % KV;
            int gm = blockRow + m;
            float4 v = make_float4(0.f, 0.f, 0.f, 0.f);
            if (gm < M) v = *(const float4*)&A[(size_t)gm * K + k0 + k4 * 4];
            As[k4 * 4 + 0][m] = v.x;
            As[k4 * 4 + 1][m] = v.y;
            As[k4 * 4 + 2][m] = v.z;
            As[k4 * 4 + 3][m] = v.w;
        }
        // load B tile (coalesced float4)
#pragma unroll
        for (int i = tid; i < BK * NV; i += THREADS) {
            int k = i / NV, n4 = i % NV;
            *(float4*)&Bs[k][n4 * 4] =
                *(const float4*)&B[(size_t)(k0 + k) * N + blockCol + n4 * 4];
        }
        __syncthreads();

#pragma unroll
        for (int kk = 0; kk < BK; kk++) {
            float ra[TM], rb[TN];
#pragma unroll
            for (int im = 0; im < TM / 4; im++) {
                float4 a4 = *(const float4*)&As[kk][tRow + im * 4];
                ra[im * 4 + 0] = a4.x; ra[im * 4 + 1] = a4.y;
                ra[im * 4 + 2] = a4.z; ra[im * 4 + 3] = a4.w;
            }
#pragma unroll
            for (int jn = 0; jn < TN / 4; jn++) {
                float4 b4 = *(const float4*)&Bs[kk][tCol + jn * 4];
                rb[jn * 4 + 0] = b4.x; rb[jn * 4 + 1] = b4.y;
                rb[jn * 4 + 2] = b4.z; rb[jn * 4 + 3] = b4.w;
            }
#pragma unroll
            for (int i = 0; i < TM; i++)
#pragma unroll
                for (int j = 0; j < TN; j++)
                    acc[i][j] = fmaf(ra[i], rb[j], acc[i][j]);
        }
        __syncthreads();
    }

#pragma unroll
    for (int i = 0; i < TM; i++) {
        int gm = blockRow + tRow + i;
        if (gm < M) {
#pragma unroll
            for (int j4 = 0; j4 < TN / 4; j4++) {
                float4 v = make_float4(acc[i][j4 * 4 + 0], acc[i][j4 * 4 + 1],
                                       acc[i][j4 * 4 + 2], acc[i][j4 * 4 + 3]);
                *(float4*)&C[(size_t)gm * N + blockCol + tCol + j4 * 4] = v;
            }
        }
    }
}

// ---------------- alpha dot products: asrc[n,h], adst[n,h] ------------------
template<int C>
__global__ void alphas_kernel(const float* __restrict__ h,
                              const float* __restrict__ a_src,
                              const float* __restrict__ a_dst,
                              float* __restrict__ asrc,
                              float* __restrict__ adst) {
    int i = blockIdx.x * blockDim.x + threadIdx.x;   // i = n*HEADS + head
    if (i >= NN * HEADS) return;
    int hh = i & (HEADS - 1);
    const float4* hp = (const float4*)(h + (size_t)(i >> 3) * (HEADS * C) + hh * C);
    const float4* s4 = (const float4*)(a_src + hh * C);
    const float4* d4 = (const float4*)(a_dst + hh * C);
    float s1 = 0.f, s2 = 0.f;
#pragma unroll
    for (int c = 0; c < C / 4; c++) {
        float4 v = hp[c];
        float4 a = s4[c];
        float4 b = d4[c];
        s1 = fmaf(v.x, a.x, fmaf(v.y, a.y, fmaf(v.z, a.z, fmaf(v.w, a.w, s1))));
        s2 = fmaf(v.x, b.x, fmaf(v.y, b.y, fmaf(v.z, b.z, fmaf(v.w, b.w, s2))));
    }
    asrc[i] = s1;
    adst[i] = s2;
}

// ---------------- CSR construction ------------------------------------------
__global__ void init_counts_kernel() {
    int i = blockIdx.x * blockDim.x + threadIdx.x;
    if (i < NN) g_counts[i] = 1;   // reserve slot for self-loop
}

__global__ void count_kernel(const int* __restrict__ dst) {
    int e = blockIdx.x * blockDim.x + threadIdx.x;
    if (e < EE) atomicAdd(&g_counts[dst[e]], 1);
}

__global__ void scan_blocks_kernel() {
    __shared__ int sh[SCAN_B];
    int t = threadIdx.x;
    int i = blockIdx.x * SCAN_B + t;
    int v = (i < NN) ? g_counts[i] : 0;
    sh[t] = v;
    __syncthreads();
    for (int off = 1; off < SCAN_B; off <<= 1) {
        int x = (t >= off) ? sh[t - off] : 0;
        __syncthreads();
        sh[t] += x;
        __syncthreads();
    }
    if (i < NN) g_rowptr[i + 1] = sh[t];
    if (t == SCAN_B - 1) g_blocksums[blockIdx.x] = sh[t];
}

// parallel exclusive scan of the 49 block sums (1 block, 64 threads)
__global__ void scan_sums_kernel() {
    __shared__ int sh[64];
    int t = threadIdx.x;
    int v = (t < NBLK) ? g_blocksums[t] : 0;
    sh[t] = v;
    __syncthreads();
    for (int off = 1; off < 64; off <<= 1) {
        int x = (t >= off) ? sh[t - off] : 0;
        __syncthreads();
        sh[t] += x;
        __syncthreads();
    }
    if (t < NBLK) g_blockoffs[t] = sh[t] - v;  // exclusive
    if (t == 0) g_rowptr[0] = 0;
}

__global__ void scan_add_kernel() {
    int i = blockIdx.x * blockDim.x + threadIdx.x;
    if (i < NN) g_rowptr[i + 1] += g_blockoffs[i / SCAN_B];
}

__global__ void place_self_kernel() {
    int i = blockIdx.x * blockDim.x + threadIdx.x;
    if (i < NN) {
        int p = g_rowptr[i];
        g_csrsrc[p] = i;        // self loop first
        g_counts[i] = p + 1;    // cursor for remaining edges
    }
}

__global__ void scatter_kernel(const int* __restrict__ src,
                               const int* __restrict__ dst) {
    int e = blockIdx.x * blockDim.x + threadIdx.x;
    if (e < EE) {
        int p = atomicAdd(&g_counts[dst[e]], 1);
        g_csrsrc[p] = src[e];
    }
}

// ---------------- aggregation: layer 1 (C=32), warp per dst node ------------
// lane l accumulates output cols [4l,4l+4) (head l>>3) and [128+4l,128+4l+4)
// (head 4+(l>>3)) as float4; 2 shuffles + 2 LDG.128 + 8 FMA per edge.
__global__ void agg1_kernel(const float* __restrict__ h,
                            const float* __restrict__ asrc,
                            const float* __restrict__ adst,
                            const float* __restrict__ bias,
                            float* __restrict__ out) {
    int warp = (blockIdx.x * blockDim.x + threadIdx.x) >> 5;
    int lane = threadIdx.x & 31;
    if (warp >= NN) return;

    int beg = g_rowptr[warp];
    int end = g_rowptr[warp + 1];
    int hsel = lane >> 3;   // head index for first chunk; second is hsel+4

    float adst_l = (lane < HEADS) ? adst[warp * HEADS + lane] : 0.f;

    // pass 1: per-head max (lanes 0..7)
    float amax_l = -INFINITY;
    for (int j = beg; j < end; j++) {
        int s = g_csrsrc[j];
        if (lane < HEADS) {
            float a = asrc[s * HEADS + lane] + adst_l;
            a = (a > 0.f) ? a : NEG * a;
            amax_l = fmaxf(amax_l, a);
        }
    }

    // pass 2: exp-sum + weighted float4 message accumulation
    float denom_l = 0.f;
    float4 acc0 = make_float4(0.f, 0.f, 0.f, 0.f);
    float4 acc1 = make_float4(0.f, 0.f, 0.f, 0.f);

    for (int j = beg; j < end; j++) {
        int s = g_csrsrc[j];
        float ex = 0.f;
        if (lane < HEADS) {
            float a = asrc[s * HEADS + lane] + adst_l;
            a = (a > 0.f) ? a : NEG * a;
            ex = __expf(a - amax_l);
            denom_l += ex;
        }
        float e0 = __shfl_sync(0xffffffffu, ex, hsel);
        float e1 = __shfl_sync(0xffffffffu, ex, hsel + 4);
        const float4* hp = (const float4*)(h + (size_t)s * HC1);
        float4 v0 = hp[lane];
        float4 v1 = hp[32 + lane];
        acc0.x = fmaf(v0.x, e0, acc0.x); acc0.y = fmaf(v0.y, e0, acc0.y);
        acc0.z = fmaf(v0.z, e0, acc0.z); acc0.w = fmaf(v0.w, e0, acc0.w);
        acc1.x = fmaf(v1.x, e1, acc1.x); acc1.y = fmaf(v1.y, e1, acc1.y);
        acc1.z = fmaf(v1.z, e1, acc1.z); acc1.w = fmaf(v1.w, e1, acc1.w);
    }

    float d0 = __shfl_sync(0xffffffffu, denom_l, hsel) + 1e-16f;
    float d1 = __shfl_sync(0xffffffffu, denom_l, hsel + 4) + 1e-16f;
    const float4* b4 = (const float4*)bias;
    float4 bb0 = b4[lane], bb1 = b4[32 + lane];

    float4 o0, o1;
    o0.x = acc0.x / d0 + bb0.x; o0.y = acc0.y / d0 + bb0.y;
    o0.z = acc0.z / d0 + bb0.z; o0.w = acc0.w / d0 + bb0.w;
    o1.x = acc1.x / d1 + bb1.x; o1.y = acc1.y / d1 + bb1.y;
    o1.z = acc1.z / d1 + bb1.z; o1.w = acc1.w / d1 + bb1.w;
    // fused inter-layer leaky relu
    o0.x = (o0.x > 0.f) ? o0.x : NEG * o0.x; o0.y = (o0.y > 0.f) ? o0.y : NEG * o0.y;
    o0.z = (o0.z > 0.f) ? o0.z : NEG * o0.z; o0.w = (o0.w > 0.f) ? o0.w : NEG * o0.w;
    o1.x = (o1.x > 0.f) ? o1.x : NEG * o1.x; o1.y = (o1.y > 0.f) ? o1.y : NEG * o1.y;
    o1.z = (o1.z > 0.f) ? o1.z : NEG * o1.z; o1.w = (o1.w > 0.f) ? o1.w : NEG * o1.w;

    float4* op = (float4*)(out + (size_t)warp * HC1);
    op[lane] = o0;
    op[32 + lane] = o1;
}

// ---------------- aggregation: layer 2 (C=4), warp per dst node -------------
// lane = head*4 + c; coalesced 128B row loads.
__global__ void agg2_kernel(const float* __restrict__ h,
                            const float* __restrict__ asrc,
                            const float* __restrict__ adst,
                            const float* __restrict__ bias,
                            float* __restrict__ out) {
    int warp = (blockIdx.x * blockDim.x + threadIdx.x) >> 5;
    int lane = threadIdx.x & 31;
    if (warp >= NN) return;

    int beg = g_rowptr[warp];
    int end = g_rowptr[warp + 1];
    int hh = lane >> 2;

    float adst_l = adst[warp * HEADS + hh];

    float amax_l = -INFINITY;
    for (int j = beg; j < end; j++) {
        int s = g_csrsrc[j];
        float a = asrc[s * HEADS + hh] + adst_l;
        a = (a > 0.f) ? a : NEG * a;
        amax_l = fmaxf(amax_l, a);
    }

    float denom_l = 0.f;
    float acc = 0.f;
    for (int j = beg; j < end; j++) {
        int s = g_csrsrc[j];
        float a = asrc[s * HEADS + hh] + adst_l;
        a = (a > 0.f) ? a : NEG * a;
        float ex = __expf(a - amax_l);
        denom_l += ex;
        acc = fmaf(h[(size_t)s * HC2 + lane], ex, acc);
    }

    out[(size_t)warp * HC2 + lane] = acc / (denom_l + 1e-16f) + bias[lane];
}

// ---------------- launch ------------------------------------------------------
extern "C" void kernel_launch(void* const* d_in, const int* in_sizes, int n_in,
                              void* d_out, int out_size) {
    const float* x      = (const float*)d_in[0];
    const int*   ei     = (const int*)d_in[1];   // [2, E]: row 0 = src, row 1 = dst
    const float* W1     = (const float*)d_in[2];
    const float* a_src1 = (const float*)d_in[3];
    const float* a_dst1 = (const float*)d_in[4];
    const float* b1     = (const float*)d_in[5];
    const float* W2     = (const float*)d_in[6];
    const float* a_src2 = (const float*)d_in[7];
    const float* a_dst2 = (const float*)d_in[8];
    const float* b2     = (const float*)d_in[9];
    float* out = (float*)d_out;

    const int* src = ei;
    const int* dst = ei + EE;

    float *h1, *o1, *h2, *as1, *ad1, *as2, *ad2;
    cudaGetSymbolAddress((void**)&h1,  g_h1);
    cudaGetSymbolAddress((void**)&o1,  g_o1);
    cudaGetSymbolAddress((void**)&h2,  g_h2);
    cudaGetSymbolAddress((void**)&as1, g_asrc1);
    cudaGetSymbolAddress((void**)&ad1, g_adst1);
    cudaGetSymbolAddress((void**)&as2, g_asrc2);
    cudaGetSymbolAddress((void**)&ad2, g_adst2);

    // --- CSR build ---
    init_counts_kernel<<<(NN + 255) / 256, 256>>>();
    count_kernel<<<(EE + 255) / 256, 256>>>(dst);
    scan_blocks_kernel<<<NBLK, SCAN_B>>>();
    scan_sums_kernel<<<1, 64>>>();
    scan_add_kernel<<<(NN + 255) / 256, 256>>>();
    place_self_kernel<<<(NN + 255) / 256, 256>>>();
    scatter_kernel<<<(EE + 255) / 256, 256>>>(src, dst);

    // --- layer 1 ---
    {
        dim3 grid(HC1 / 128, (NN + 127) / 128);
        sgemm_kernel<128, 128, 16, 8, 8><<<grid, 256>>>(NN, HC1, FIN, x, W1, h1);
    }
    alphas_kernel<HID><<<(NN * HEADS + 255) / 256, 256>>>(h1, a_src1, a_dst1, as1, ad1);
    agg1_kernel<<<(NN * 32 + 255) / 256, 256>>>(h1, as1, ad1, b1, o1);

    // --- layer 2 ---
    {
        dim3 grid(HC2 / 32, (NN + 127) / 128);
        sgemm_kernel<128, 32, 32, 8, 4><<<grid, 128>>>(NN, HC2, HC1, o1, W2, h2);
    }
    alphas_kernel<OUTC><<<(NN * HEADS + 255) / 256, 256>>>(h2, a_src2, a_dst2, as2, ad2);
    agg2_kernel<<<(NN * 32 + 255) / 256, 256>>>(h2, as2, ad2, b2, out);
}